// round 13
// baseline (speedup 1.0000x reference)
#include <cuda_runtime.h>

// ---------------------------------------------------------------------------
// EResidualBlockBucket: x -> grouped3x3+ReLU -> per-pixel bucket-indexed
// dynamic 3x3 conv (+per-pixel bias) -> ReLU -> 1x1 conv -> +x -> ReLU
//
// R10 lesson: per-icc weight staging from DRAM is the floor (67-81us across
// 5 variants). R11: load the ENTIRE 147.7KB per-bucket filter with ONE
// cp.async.bulk (TMA) into smem (B200: 227KB/CTA), stage ALL 576-channel
// patches for a 32-pixel chunk once (76KB), then compute with ZERO weight
// restaging and 4 barriers per chunk. Weight rows keep gmem layout; each
// warp owns 4 ocs of equal residue mod 4 so LDS.128 stays 16B-aligned via
// a per-warp c-phase. Pixel lists built by a tiny pre-kernel (smem is full).
// ---------------------------------------------------------------------------

#define HPW 66                 // padded image width/height
#define HPSZ (64 * HPW * HPW)  // h_pad elements: [y][x][ic], ic fastest

__device__ __align__(16) float g_hpad[HPSZ];     // padded h, pixel-major
__device__ int g_cnt[216];                        // pixels per bucket
__device__ unsigned short g_plist[216 * 4096];    // pixel lists (stride 4096)

// dynamic smem layout (bytes)
#define SM_W    0                          // W tile: 64*577*4 = 147712
#define SM_PS   147712                     // patches: 576*33*4 = 76032
#define SM_MBAR 223744                     // mbarrier (8B)
#define SM_TOT  223760

// ---------------- K0: bucket sort (one CTA) --------------------------------
__global__ void __launch_bounds__(1024) k_sort(const int* __restrict__ buckets) {
    __shared__ int cnt[216];
    int tid = threadIdx.x;
    if (tid < 216) cnt[tid] = 0;
    __syncthreads();
    for (int i = tid; i < 4096; i += 1024) {
        int t = buckets[i];
        if ((unsigned)t < 216u) {
            int p = atomicAdd(&cnt[t], 1);
            g_plist[t * 4096 + p] = (unsigned short)i;
        }
    }
    __syncthreads();
    if (tid < 216) g_cnt[tid] = cnt[tid];
}

// ---------------- K1: grouped 3x3 conv + bias + ReLU -> g_hpad -------------
__global__ void __launch_bounds__(256) k_gconv(const float* __restrict__ x,
                                               const float* __restrict__ w1,
                                               const float* __restrict__ b1) {
    __shared__ float xs[16][18][18];
    __shared__ float ws[16][144];
    __shared__ float bs[16];

    int bx = blockIdx.x;
    int g = bx >> 4;
    int tile = bx & 15;
    int y0 = (tile >> 2) * 16, x0 = (tile & 3) * 16;
    int tid = threadIdx.x;

    for (int i = tid; i < 16 * 18 * 18; i += 256) {
        int ic = i / 324;
        int rem = i - ic * 324;
        int r = rem / 18, c = rem - r * 18;
        int yy = y0 - 1 + r, xx = x0 - 1 + c;
        float v = 0.f;
        if (yy >= 0 && yy < 64 && xx >= 0 && xx < 64)
            v = x[(g * 16 + ic) * 4096 + yy * 64 + xx];
        xs[ic][r][c] = v;
    }
    for (int i = tid; i < 16 * 144; i += 256) {
        int oc = i / 144;
        ws[oc][i - oc * 144] = w1[(g * 16 + oc) * 144 + (i - oc * 144)];
    }
    if (tid < 16) bs[tid] = b1[g * 16 + tid];
    __syncthreads();

    int r = tid >> 4, c = tid & 15;
    float acc[16];
#pragma unroll
    for (int j = 0; j < 16; ++j) acc[j] = bs[j];

    for (int ic = 0; ic < 16; ++ic) {
        float p[9];
#pragma unroll
        for (int dy = 0; dy < 3; ++dy)
#pragma unroll
            for (int dx = 0; dx < 3; ++dx)
                p[dy * 3 + dx] = xs[ic][r + dy][c + dx];
#pragma unroll
        for (int j = 0; j < 16; ++j) {
#pragma unroll
            for (int k = 0; k < 9; ++k)
                acc[j] = fmaf(ws[j][ic * 9 + k], p[k], acc[j]);
        }
    }
    float* dst = g_hpad + (((y0 + r + 1) * HPW) + (x0 + c + 1)) * 64 + g * 16;
#pragma unroll
    for (int j = 0; j < 16; ++j) dst[j] = fmaxf(acc[j], 0.f);
}

// ---------------- K2: bucket-grouped dynamic conv + fused epilogue ---------
// grid 216 x 512 threads (16 warps). Warp w owns ocs {oc0 + 16j, j=0..3},
// oc0 = (w&3) + 4*(w>>2): all 4 ocs share residue (w&3) mod 4 so weight
// LDS.128 at 4*(oc*577 + c) is 16B-aligned for c = c0 + 4m, c0 = (-oc)&3.
__global__ void __launch_bounds__(512)
k_dyn(const float* __restrict__ emb, const float* __restrict__ x,
      const float* __restrict__ w2, const float* __restrict__ b2,
      float* __restrict__ out) {
    extern __shared__ __align__(16) char sm[];
    float* wsm = (float*)(sm + SM_W);            // W tile, gmem layout
    float* ps  = (float*)(sm + SM_PS);           // patches [c][slot] pitch 33
    unsigned mbar = (unsigned)__cvta_generic_to_shared(sm + SM_MBAR);

    int t = blockIdx.x;
    int tid = threadIdx.x;
    int n = __ldg(&g_cnt[t]);
    if (n == 0) return;

    int lane = tid & 31;
    int wid = tid >> 5;                          // 0..15
    int r4 = wid & 3;
    int oc0 = r4 + 4 * (wid >> 2);               // ocs oc0 + 16j
    int c0 = (4 - r4) & 3;                       // quad phase
    const float* W = emb + (size_t)t * 36928;
    const unsigned short* plist = g_plist + t * 4096;

    // ---- kick off TMA bulk load of the whole W tile (147712 B) ----
    if (tid == 0) {
        asm volatile("mbarrier.init.shared.b64 [%0], 1;" :: "r"(mbar));
        // make init visible to the async proxy before the bulk op
        asm volatile("fence.proxy.async.shared::cta;" ::: "memory");
        asm volatile("mbarrier.arrive.expect_tx.shared.b64 _, [%0], %1;"
                     :: "r"(mbar), "r"(147712u));
        unsigned wdst = (unsigned)__cvta_generic_to_shared(sm + SM_W);
#pragma unroll
        for (int q = 0; q < 4; ++q) {            // 4 x 36928 B pieces
            asm volatile(
                "cp.async.bulk.shared::cluster.global.mbarrier::complete_tx::bytes"
                " [%0], [%1], %2, [%3];"
                :: "r"(wdst + q * 36928u),
                   "l"((const void*)((const char*)W + q * 36928)),
                   "r"(36928u), "r"(mbar) : "memory");
        }
    }

    // ---- per-thread invariant patch-staging indices ----
    // 4608 float4 items: item i -> q=i&15 (ic quad), r=i>>4, slot=r/9, pos=r%9
    int sq[9], sslot[9], sps[9], sgp[9];
#pragma unroll
    for (int k = 0; k < 9; ++k) {
        int i = tid + 512 * k;
        int q = i & 15;
        int r = i >> 4;
        int slot = r / 9, pos = r - slot * 9;
        int dy = pos / 3, dx = pos - dy * 3;
        sq[k] = q; sslot[k] = slot;
        sps[k] = ((4 * q) * 9 + pos) * 33 + slot;     // + j*9*33 for j
        sgp[k] = (dy * HPW + dx) * 64 + 4 * q;
    }

    // hoisted per-bucket constants
    float bias[4], eb[4];
#pragma unroll
    for (int j = 0; j < 4; ++j) {
        bias[j] = __ldg(W + (oc0 + 16 * j) * 577 + 576);
        eb[j]   = __ldg(b2 + oc0 + 16 * j);
    }

    bool first = true;
    for (int chunk = 0; chunk < n; chunk += 32) {
        int pi = chunk + lane;
        int mypix = __ldg(plist + (pi < n ? pi : n - 1));

        // ---- stage ALL patches for this chunk: 9 float4 items/thread ----
#pragma unroll
        for (int k = 0; k < 9; ++k) {
            int pj = chunk + sslot[k];
            int pix = __ldg(plist + (pj < n ? pj : n - 1));
            const float4 v = *(const float4*)(g_hpad +
                ((pix >> 6) * HPW + (pix & 63)) * 64 + sgp[k]);
            int o = sps[k];
            ps[o +   0] = v.x;     // c = (4q+0)*9+pos
            ps[o + 297] = v.y;     // +9*33
            ps[o + 594] = v.z;
            ps[o + 891] = v.w;
        }
        __syncthreads();

        if (first) {               // wait once for the W TMA
            first = false;
            unsigned done;
            do {
                asm volatile(
                    "{\n\t.reg .pred p;\n\t"
                    "mbarrier.try_wait.parity.acquire.cta.shared::cta.b64 p, [%1], 0, 0x989680;\n\t"
                    "selp.b32 %0, 1, 0, p;\n\t}"
                    : "=r"(done) : "r"(mbar) : "memory");
            } while (!done);
        }

        // ---- compute: 143 aligned c-quads + 4 wrap scalars ----
        float acc[4] = { bias[0], bias[1], bias[2], bias[3] };
        const float* psl = ps + lane;
#pragma unroll 4
        for (int m = 0; m < 143; ++m) {
            int c = c0 + 4 * m;
            float p0 = psl[(c + 0) * 33];
            float p1 = psl[(c + 1) * 33];
            float p2 = psl[(c + 2) * 33];
            float p3 = psl[(c + 3) * 33];
#pragma unroll
            for (int j = 0; j < 4; ++j) {
                const float4 w = *(const float4*)(wsm + (oc0 + 16 * j) * 577 + c);
                acc[j] = fmaf(w.x, p0, acc[j]);
                acc[j] = fmaf(w.y, p1, acc[j]);
                acc[j] = fmaf(w.z, p2, acc[j]);
                acc[j] = fmaf(w.w, p3, acc[j]);
            }
        }
#pragma unroll
        for (int k = 0; k < 4; ++k) {            // leftover c's (wrap)
            int c = c0 + 572 + k;
            if (c >= 576) c -= 576;
            float pe = psl[c * 33];
#pragma unroll
            for (int j = 0; j < 4; ++j)
                acc[j] = fmaf(wsm[(oc0 + 16 * j) * 577 + c], pe, acc[j]);
        }
        __syncthreads();           // ps reads done before ds overlay

        // ---- fused epilogue: ReLU -> 1x1 conv (w2) + b2 -> +x -> ReLU ----
        float* ds = ps;            // 64*33 floats overlay
#pragma unroll
        for (int j = 0; j < 4; ++j)
            ds[(oc0 + 16 * j) * 33 + lane] = fmaxf(acc[j], 0.f);
        __syncthreads();

        float eacc[4] = { eb[0], eb[1], eb[2], eb[3] };
#pragma unroll
        for (int blk = 0; blk < 4; ++blk) {
            float pv[16];
#pragma unroll
            for (int q = 0; q < 16; ++q)
                pv[q] = ds[(blk * 16 + q) * 33 + lane];
#pragma unroll
            for (int j = 0; j < 4; ++j) {
                const float4* wr = (const float4*)(w2 +
                    (oc0 + 16 * j) * 64 + blk * 16);
#pragma unroll
                for (int q4 = 0; q4 < 4; ++q4) {
                    float4 w = __ldg(wr + q4);
                    eacc[j] = fmaf(w.x, pv[q4 * 4 + 0], eacc[j]);
                    eacc[j] = fmaf(w.y, pv[q4 * 4 + 1], eacc[j]);
                    eacc[j] = fmaf(w.z, pv[q4 * 4 + 2], eacc[j]);
                    eacc[j] = fmaf(w.w, pv[q4 * 4 + 3], eacc[j]);
                }
            }
        }

        if (pi < n) {
#pragma unroll
            for (int j = 0; j < 4; ++j) {
                int o = oc0 + 16 * j;
                out[o * 4096 + mypix] =
                    fmaxf(eacc[j] + __ldg(x + o * 4096 + mypix), 0.f);
            }
        }
        __syncthreads();           // ds (= ps) drains before next chunk
    }
}

// ---------------------------------------------------------------------------
extern "C" void kernel_launch(void* const* d_in, const int* in_sizes, int n_in,
                              void* d_out, int out_size) {
    const float* x       = (const float*)d_in[0];
    const int*   buckets = (const int*)  d_in[1];
    const float* w1      = (const float*)d_in[2];
    const float* b1      = (const float*)d_in[3];
    const float* emb     = (const float*)d_in[4];
    const float* w2      = (const float*)d_in[5];
    const float* b2      = (const float*)d_in[6];
    float* out = (float*)d_out;

    cudaFuncSetAttribute(k_dyn, cudaFuncAttributeMaxDynamicSharedMemorySize,
                         SM_TOT);

    k_sort<<<1, 1024>>>(buckets);
    k_gconv<<<64, 256>>>(x, w1, b1);
    k_dyn<<<216, 512, SM_TOT>>>(emb, x, w2, b2, out);
}